// round 1
// baseline (speedup 1.0000x reference)
#include <cuda_runtime.h>
#include <math.h>

#define Bb 2
#define Tt 2048
#define Cc 768
#define Hh 12
#define Dd 64
#define BH (Bb*Hh)      /* 24 */
#define Mrows (Bb*Tt)   /* 4096 */

// Scratch (device globals — no runtime allocation allowed)
__device__ float g_q[(size_t)BH*Tt*Dd];
__device__ float g_k[(size_t)BH*Tt*Dd];
__device__ float g_v[(size_t)BH*Tt*Dd];
__device__ float g_y[(size_t)BH*Tt*Dd];

// ---------------------------------------------------------------------------
// QKV projection: out = x @ W^T  (NT GEMM, M=4096, N=768, K=768)
// scattered into [B,H,T,D]. blockIdx.z selects q/k/v.
// ---------------------------------------------------------------------------
__global__ __launch_bounds__(256) void qkv_kernel(
    const float* __restrict__ x,
    const float* __restrict__ Wq,
    const float* __restrict__ Wk,
    const float* __restrict__ Wv)
{
    const float* W  = (blockIdx.z == 0) ? Wq : ((blockIdx.z == 1) ? Wk : Wv);
    float*       out = (blockIdx.z == 0) ? g_q : ((blockIdx.z == 1) ? g_k : g_v);

    __shared__ float As[16][128];
    __shared__ float Bs[16][128];

    const int m0 = blockIdx.y * 128;
    const int n0 = blockIdx.x * 128;
    const int tid = threadIdx.x;
    const int tx = tid & 15, ty = tid >> 4;
    const int lr = tid >> 2, lc = (tid & 3) * 4;

    float acc[8][8];
    #pragma unroll
    for (int i = 0; i < 8; i++)
        #pragma unroll
        for (int j = 0; j < 8; j++) acc[i][j] = 0.f;

    for (int k0 = 0; k0 < Cc; k0 += 16) {
        float4 a0 = *(const float4*)(x + (size_t)(m0 + lr)      * Cc + k0 + lc);
        float4 a1 = *(const float4*)(x + (size_t)(m0 + lr + 64) * Cc + k0 + lc);
        float4 b0 = *(const float4*)(W + (size_t)(n0 + lr)      * Cc + k0 + lc);
        float4 b1 = *(const float4*)(W + (size_t)(n0 + lr + 64) * Cc + k0 + lc);
        __syncthreads();
        As[lc+0][lr]    = a0.x; As[lc+1][lr]    = a0.y; As[lc+2][lr]    = a0.z; As[lc+3][lr]    = a0.w;
        As[lc+0][lr+64] = a1.x; As[lc+1][lr+64] = a1.y; As[lc+2][lr+64] = a1.z; As[lc+3][lr+64] = a1.w;
        Bs[lc+0][lr]    = b0.x; Bs[lc+1][lr]    = b0.y; Bs[lc+2][lr]    = b0.z; Bs[lc+3][lr]    = b0.w;
        Bs[lc+0][lr+64] = b1.x; Bs[lc+1][lr+64] = b1.y; Bs[lc+2][lr+64] = b1.z; Bs[lc+3][lr+64] = b1.w;
        __syncthreads();
        #pragma unroll
        for (int kk = 0; kk < 16; kk++) {
            float ra[8], rb[8];
            *(float4*)&ra[0] = *(const float4*)&As[kk][ty*8];
            *(float4*)&ra[4] = *(const float4*)&As[kk][ty*8+4];
            *(float4*)&rb[0] = *(const float4*)&Bs[kk][tx*8];
            *(float4*)&rb[4] = *(const float4*)&Bs[kk][tx*8+4];
            #pragma unroll
            for (int i = 0; i < 8; i++)
                #pragma unroll
                for (int j = 0; j < 8; j++) acc[i][j] += ra[i] * rb[j];
        }
    }

    #pragma unroll
    for (int i = 0; i < 8; i++) {
        const int m = m0 + ty*8 + i;
        const int b = m >> 11, t = m & (Tt - 1);
        #pragma unroll
        for (int j = 0; j < 8; j++) {
            const int n = n0 + tx*8 + j;
            const int h = n >> 6, d = n & 63;
            out[(((size_t)(b*Hh + h))*Tt + t)*Dd + d] = acc[i][j];
        }
    }
}

// ---------------------------------------------------------------------------
// RoPE on q and k in place. Thread handles the (p, p+16) pair of one row.
// ---------------------------------------------------------------------------
__global__ __launch_bounds__(256) void rope_kernel()
{
    const int idx = blockIdx.x * 256 + threadIdx.x;
    const int total = BH * Tt * 16;
    if (idx >= total) return;
    const int p   = idx & 15;
    const int row = idx >> 4;
    const int t   = row & (Tt - 1);

    const float L2_1E4_OVER_32 = 0.41524101186092028f; // log2(10000)/32
    const float f1 = exp2f(-(float)p        * L2_1E4_OVER_32);
    const float f2 = exp2f(-(float)(p + 16) * L2_1E4_OVER_32);
    float s1, c1, s2, c2;
    sincosf((float)t * f1, &s1, &c1);
    sincosf((float)t * f2, &s2, &c2);

    float* q = g_q + (size_t)row * Dd;
    float* k = g_k + (size_t)row * Dd;
    const float qa = q[p], qb = q[p + 16];
    q[p]      = qa * c1 - qb * s1;
    q[p + 16] = qb * c2 + qa * s2;
    const float ka = k[p], kb = k[p + 16];
    k[p]      = ka * c1 - kb * s1;
    k[p + 16] = kb * c2 + ka * s2;
}

// ---------------------------------------------------------------------------
// Causal logits: att_raw[m,n] = scale * q[m]·k[n] + rel_bias[m-n+T-1, h]
// Writes only n <= m. Upper-triangle tiles skipped entirely.
// ---------------------------------------------------------------------------
__global__ __launch_bounds__(256) void logits_kernel(
    const float* __restrict__ rel_bias, float* __restrict__ att)
{
    const int kt = blockIdx.x, qt = blockIdx.y, bh = blockIdx.z;
    if (kt > qt) return;
    const int h = bh % Hh;
    const float* Q  = g_q + (size_t)bh * Tt * Dd;
    const float* Kp = g_k + (size_t)bh * Tt * Dd;
    float* A = att + (size_t)bh * Tt * Tt;

    __shared__ float Qs[32][128];
    __shared__ float Ks[32][128];

    const int tid = threadIdx.x;
    const int tx = tid & 15, ty = tid >> 4;
    const int lr = tid >> 3, lc = (tid & 7) * 4;

    float acc[8][8];
    #pragma unroll
    for (int i = 0; i < 8; i++)
        #pragma unroll
        for (int j = 0; j < 8; j++) acc[i][j] = 0.f;

    for (int k0 = 0; k0 < Dd; k0 += 32) {
        float4 qv[4], kv[4];
        #pragma unroll
        for (int s = 0; s < 4; s++) {
            qv[s] = *(const float4*)(Q  + (size_t)(qt*128 + lr + 32*s)*Dd + k0 + lc);
            kv[s] = *(const float4*)(Kp + (size_t)(kt*128 + lr + 32*s)*Dd + k0 + lc);
        }
        __syncthreads();
        #pragma unroll
        for (int s = 0; s < 4; s++) {
            const int r = lr + 32*s;
            Qs[lc+0][r] = qv[s].x; Qs[lc+1][r] = qv[s].y; Qs[lc+2][r] = qv[s].z; Qs[lc+3][r] = qv[s].w;
            Ks[lc+0][r] = kv[s].x; Ks[lc+1][r] = kv[s].y; Ks[lc+2][r] = kv[s].z; Ks[lc+3][r] = kv[s].w;
        }
        __syncthreads();
        #pragma unroll
        for (int kk = 0; kk < 32; kk++) {
            float ra[8], rb[8];
            *(float4*)&ra[0] = *(const float4*)&Qs[kk][ty*8];
            *(float4*)&ra[4] = *(const float4*)&Qs[kk][ty*8+4];
            *(float4*)&rb[0] = *(const float4*)&Ks[kk][tx*8];
            *(float4*)&rb[4] = *(const float4*)&Ks[kk][tx*8+4];
            #pragma unroll
            for (int i = 0; i < 8; i++)
                #pragma unroll
                for (int j = 0; j < 8; j++) acc[i][j] += ra[i] * rb[j];
        }
    }

    #pragma unroll
    for (int i = 0; i < 8; i++) {
        const int m = qt*128 + ty*8 + i;
        #pragma unroll
        for (int j = 0; j < 8; j++) {
            const int n = kt*128 + tx*8 + j;
            if (n <= m) {
                A[(size_t)m*Tt + n] =
                    acc[i][j] * 0.125f + __ldg(&rel_bias[(size_t)(m - n + Tt - 1)*Hh + h]);
            }
        }
    }
}

// ---------------------------------------------------------------------------
// Row softmax in place: one block per (bh, m) row. Full row kept in smem.
// Writes exact zeros for n > m (causal mask output).
// ---------------------------------------------------------------------------
__global__ __launch_bounds__(256) void softmax_kernel(float* __restrict__ att)
{
    const int row = blockIdx.x;            // bh*T + m
    const int m = row & (Tt - 1);
    float* A = att + (size_t)row * Tt;
    __shared__ float buf[Tt];
    __shared__ float red[8];
    const int tid = threadIdx.x;
    const int L = m + 1;

    float mx = -INFINITY;
    for (int j = tid; j < Tt; j += 256) {
        const float v = (j < L) ? A[j] : -INFINITY;
        buf[j] = v;
        mx = fmaxf(mx, v);
    }
    #pragma unroll
    for (int o = 16; o; o >>= 1) mx = fmaxf(mx, __shfl_xor_sync(0xffffffffu, mx, o));
    if ((tid & 31) == 0) red[tid >> 5] = mx;
    __syncthreads();
    mx = red[0];
    #pragma unroll
    for (int w = 1; w < 8; w++) mx = fmaxf(mx, red[w]);
    __syncthreads();

    float s = 0.f;
    for (int j = tid; j < Tt; j += 256) {
        const float e = (j < L) ? __expf(buf[j] - mx) : 0.f;
        buf[j] = e;
        s += e;
    }
    #pragma unroll
    for (int o = 16; o; o >>= 1) s += __shfl_xor_sync(0xffffffffu, s, o);
    if ((tid & 31) == 0) red[tid >> 5] = s;
    __syncthreads();
    s = red[0];
    #pragma unroll
    for (int w = 1; w < 8; w++) s += red[w];
    const float inv = 1.f / s;
    for (int j = tid; j < Tt; j += 256) A[j] = buf[j] * inv;
}

// ---------------------------------------------------------------------------
// y = att @ v per (b,h). NN GEMM, M=2048, N=64, K causal-limited.
// ---------------------------------------------------------------------------
__global__ __launch_bounds__(256) void av_kernel(const float* __restrict__ att)
{
    const int mt = blockIdx.x, bh = blockIdx.y;
    const float* A = att + (size_t)bh * Tt * Tt;
    const float* V = g_v + (size_t)bh * Tt * Dd;
    float* Y = g_y + (size_t)bh * Tt * Dd;

    __shared__ float As[32][128];
    __shared__ float Vs[32][64];

    const int tid = threadIdx.x;
    const int tx = tid & 15, ty = tid >> 4;
    const int lr = tid >> 3, lc = (tid & 7) * 4;   // A loads
    const int vr = tid >> 4, vc = (tid & 15) * 4;  // V loads

    float acc[8][4];
    #pragma unroll
    for (int i = 0; i < 8; i++)
        #pragma unroll
        for (int j = 0; j < 4; j++) acc[i][j] = 0.f;

    const int nk = (mt + 1) * 4;   // K tiles of 32 up to the causal boundary
    for (int kt = 0; kt < nk; kt++) {
        const int j0 = kt * 32;
        float4 av4[4];
        #pragma unroll
        for (int s = 0; s < 4; s++)
            av4[s] = *(const float4*)(A + (size_t)(mt*128 + lr + 32*s)*Tt + j0 + lc);
        float4 vv0 = *(const float4*)(V + (size_t)(j0 + vr)      * Dd + vc);
        float4 vv1 = *(const float4*)(V + (size_t)(j0 + vr + 16) * Dd + vc);
        __syncthreads();
        #pragma unroll
        for (int s = 0; s < 4; s++) {
            const int r = lr + 32*s;
            As[lc+0][r] = av4[s].x; As[lc+1][r] = av4[s].y; As[lc+2][r] = av4[s].z; As[lc+3][r] = av4[s].w;
        }
        *(float4*)&Vs[vr][vc]      = vv0;
        *(float4*)&Vs[vr + 16][vc] = vv1;
        __syncthreads();
        #pragma unroll
        for (int kk = 0; kk < 32; kk++) {
            float ra[8], rb[4];
            *(float4*)&ra[0] = *(const float4*)&As[kk][ty*8];
            *(float4*)&ra[4] = *(const float4*)&As[kk][ty*8+4];
            *(float4*)&rb[0] = *(const float4*)&Vs[kk][tx*4];
            #pragma unroll
            for (int i = 0; i < 8; i++)
                #pragma unroll
                for (int j = 0; j < 4; j++) acc[i][j] += ra[i] * rb[j];
        }
    }

    #pragma unroll
    for (int i = 0; i < 8; i++)
        #pragma unroll
        for (int j = 0; j < 4; j++)
            Y[(size_t)(mt*128 + ty*8 + i)*Dd + tx*4 + j] = acc[i][j];
}

// ---------------------------------------------------------------------------
// Output projection: y[m,n] = sum_k yatt[m,k] * Wp[n,k] + bp[n]
// yatt gathered from g_y [B,H,T,D].
// ---------------------------------------------------------------------------
__global__ __launch_bounds__(256) void proj_kernel(
    const float* __restrict__ Wp, const float* __restrict__ bp,
    float* __restrict__ y)
{
    __shared__ float As[16][128];
    __shared__ float Bs[16][128];

    const int m0 = blockIdx.y * 128;
    const int n0 = blockIdx.x * 128;
    const int tid = threadIdx.x;
    const int tx = tid & 15, ty = tid >> 4;
    const int lr = tid >> 2, lc = (tid & 3) * 4;

    float acc[8][8];
    #pragma unroll
    for (int i = 0; i < 8; i++)
        #pragma unroll
        for (int j = 0; j < 8; j++) acc[i][j] = 0.f;

    for (int k0 = 0; k0 < Cc; k0 += 16) {
        const int k = k0 + lc;
        const int h = k >> 6, d = k & 63;
        int m = m0 + lr;
        int b = m >> 11, t = m & (Tt - 1);
        float4 a0 = *(const float4*)(g_y + ((size_t)(b*Hh + h)*Tt + t)*Dd + d);
        m = m0 + lr + 64; b = m >> 11; t = m & (Tt - 1);
        float4 a1 = *(const float4*)(g_y + ((size_t)(b*Hh + h)*Tt + t)*Dd + d);
        float4 b0 = *(const float4*)(Wp + (size_t)(n0 + lr)      * Cc + k);
        float4 b1 = *(const float4*)(Wp + (size_t)(n0 + lr + 64) * Cc + k);
        __syncthreads();
        As[lc+0][lr]    = a0.x; As[lc+1][lr]    = a0.y; As[lc+2][lr]    = a0.z; As[lc+3][lr]    = a0.w;
        As[lc+0][lr+64] = a1.x; As[lc+1][lr+64] = a1.y; As[lc+2][lr+64] = a1.z; As[lc+3][lr+64] = a1.w;
        Bs[lc+0][lr]    = b0.x; Bs[lc+1][lr]    = b0.y; Bs[lc+2][lr]    = b0.z; Bs[lc+3][lr]    = b0.w;
        Bs[lc+0][lr+64] = b1.x; Bs[lc+1][lr+64] = b1.y; Bs[lc+2][lr+64] = b1.z; Bs[lc+3][lr+64] = b1.w;
        __syncthreads();
        #pragma unroll
        for (int kk = 0; kk < 16; kk++) {
            float ra[8], rb[8];
            *(float4*)&ra[0] = *(const float4*)&As[kk][ty*8];
            *(float4*)&ra[4] = *(const float4*)&As[kk][ty*8+4];
            *(float4*)&rb[0] = *(const float4*)&Bs[kk][tx*8];
            *(float4*)&rb[4] = *(const float4*)&Bs[kk][tx*8+4];
            #pragma unroll
            for (int i = 0; i < 8; i++)
                #pragma unroll
                for (int j = 0; j < 8; j++) acc[i][j] += ra[i] * rb[j];
        }
    }

    #pragma unroll
    for (int i = 0; i < 8; i++) {
        const int m = m0 + ty*8 + i;
        #pragma unroll
        for (int j = 0; j < 8; j++) {
            const int n = n0 + tx*8 + j;
            y[(size_t)m*Cc + n] = acc[i][j] + bp[n];
        }
    }
}

// ---------------------------------------------------------------------------
extern "C" void kernel_launch(void* const* d_in, const int* in_sizes, int n_in,
                              void* d_out, int out_size)
{
    (void)in_sizes; (void)n_in; (void)out_size;
    const float* x  = (const float*)d_in[0];
    const float* Wq = (const float*)d_in[1];
    const float* Wk = (const float*)d_in[2];
    const float* Wv = (const float*)d_in[3];
    const float* Wp = (const float*)d_in[4];
    const float* bp = (const float*)d_in[5];
    const float* rb = (const float*)d_in[6];
    float* y   = (float*)d_out;                         // [B,T,C]
    float* att = y + (size_t)Bb * Tt * Cc;              // [B,H,T,T]

    qkv_kernel   <<<dim3(6, 32, 3), 256>>>(x, Wq, Wk, Wv);
    rope_kernel  <<<(BH*Tt*16 + 255)/256, 256>>>();
    logits_kernel<<<dim3(16, 16, BH), 256>>>(rb, att);
    softmax_kernel<<<BH*Tt, 256>>>(att);
    av_kernel    <<<dim3(16, BH), 256>>>(att);
    proj_kernel  <<<dim3(6, 32), 256>>>(Wp, bp, y);
}

// round 3
// speedup vs baseline: 1.9183x; 1.9183x over previous
#include <cuda_runtime.h>
#include <cuda_bf16.h>
#include <math.h>
#include <stdint.h>

#define Bb 2
#define Tt 2048
#define Cc 768
#define Hh 12
#define Dd 64
#define NBH (Bb*Hh)

// ---------------- scratch (device globals; no runtime allocation) ----------
__device__ float g_q[(size_t)NBH*Tt*Dd];
__device__ float g_k[(size_t)NBH*Tt*Dd];
__device__ float g_v[(size_t)NBH*Tt*Dd];
__device__ __nv_bfloat16 g_x_hi[(size_t)4096*768];
__device__ __nv_bfloat16 g_x_lo[(size_t)4096*768];
__device__ __nv_bfloat16 g_w_hi[(size_t)4*768*768];
__device__ __nv_bfloat16 g_w_lo[(size_t)4*768*768];
__device__ __nv_bfloat16 g_q_hi[(size_t)NBH*Tt*Dd];
__device__ __nv_bfloat16 g_q_lo[(size_t)NBH*Tt*Dd];
__device__ __nv_bfloat16 g_k_hi[(size_t)NBH*Tt*Dd];
__device__ __nv_bfloat16 g_k_lo[(size_t)NBH*Tt*Dd];
__device__ __nv_bfloat16 g_vT_hi[(size_t)NBH*Dd*Tt];
__device__ __nv_bfloat16 g_vT_lo[(size_t)NBH*Dd*Tt];
__device__ __nv_bfloat16 g_y_hi[(size_t)NBH*Tt*Dd];
__device__ __nv_bfloat16 g_y_lo[(size_t)NBH*Tt*Dd];
__device__ float g_rope[(size_t)Tt*64];

// ---------------- helpers ---------------------------------------------------
__device__ __forceinline__ uint32_t smem_u32(const void* p) {
    uint32_t a;
    asm("{ .reg .u64 t; cvta.to.shared.u64 t, %1; cvt.u32.u64 %0, t; }" : "=r"(a) : "l"(p));
    return a;
}
__device__ __forceinline__ void cpa16(uint32_t d, const void* s) {
    asm volatile("cp.async.cg.shared.global [%0], [%1], 16;" :: "r"(d), "l"(s));
}
__device__ __forceinline__ void cp_commit() { asm volatile("cp.async.commit_group;" ::: "memory"); }
__device__ __forceinline__ void cp_wait0()  { asm volatile("cp.async.wait_group 0;" ::: "memory"); }
__device__ __forceinline__ void cp_wait1()  { asm volatile("cp.async.wait_group 1;" ::: "memory"); }
__device__ __forceinline__ void ldmat4(uint32_t* r, uint32_t a) {
    asm volatile("ldmatrix.sync.aligned.m8n8.x4.shared.b16 {%0,%1,%2,%3}, [%4];"
                 : "=r"(r[0]), "=r"(r[1]), "=r"(r[2]), "=r"(r[3]) : "r"(a));
}
__device__ __forceinline__ void mma_bf16(float* c, const uint32_t* a, const uint32_t* b) {
    asm volatile("mma.sync.aligned.m16n8k16.row.col.f32.bf16.bf16.f32 "
                 "{%0,%1,%2,%3}, {%4,%5,%6,%7}, {%8,%9}, {%0,%1,%2,%3};"
                 : "+f"(c[0]), "+f"(c[1]), "+f"(c[2]), "+f"(c[3])
                 : "r"(a[0]), "r"(a[1]), "r"(a[2]), "r"(a[3]), "r"(b[0]), "r"(b[1]));
}
__device__ __forceinline__ uint32_t packbf2(float a, float b) {
    __nv_bfloat162 t = __floats2bfloat162_rn(a, b);
    return reinterpret_cast<uint32_t&>(t);
}
__device__ __forceinline__ void split2u(float a, float b, uint32_t& hi, uint32_t& lo) {
    float ah = __bfloat162float(__float2bfloat16(a));
    float bh = __bfloat162float(__float2bfloat16(b));
    hi = packbf2(ah, bh);
    lo = packbf2(a - ah, b - bh);
}
// split a float4 -> two packed-bf16x2 pairs (uint2) for hi and lo planes
__device__ __forceinline__ void split4(float4 f, uint2& hi, uint2& lo) {
    split2u(f.x, f.y, hi.x, lo.x);
    split2u(f.z, f.w, hi.y, lo.y);
}

// cp.async issue: A-hi/A-lo/B-hi/B-lo tiles, 4x16B per plane per thread.
// tile row stride = 144 bytes (72 bf16), plane stride 18432 bytes.
__device__ __forceinline__ void issue4(uint32_t dbase,
    const __nv_bfloat16* s0, const __nv_bfloat16* s1,
    const __nv_bfloat16* s2, const __nv_bfloat16* s3) {
    #pragma unroll
    for (int j = 0; j < 4; j++) {
        cpa16(dbase + 0u*18432u + j*16, s0 + j*8);
        cpa16(dbase + 1u*18432u + j*16, s1 + j*8);
        cpa16(dbase + 2u*18432u + j*16, s2 + j*8);
        cpa16(dbase + 3u*18432u + j*16, s3 + j*8);
    }
    cp_commit();
}

// one k=64 chunk, CTA tile 128x128, warp tile 64x32 (wr in {0,1}, wc in 0..3)
__device__ __forceinline__ void consume_128x128(
    uint32_t AH, uint32_t AL, uint32_t BH, uint32_t BL,
    int wr, int wc, int lane, float (&acc)[4][4][4]) {
    #pragma unroll
    for (int half = 0; half < 2; half++) {
        uint32_t bh[4][4], bl[4][4];
        #pragma unroll
        for (int j = 0; j < 4; j++) {
            uint32_t off = (uint32_t)((wc*32 + j*8 + (lane & 7)) * 144 + half*64 + ((lane >> 3) & 3) * 16);
            ldmat4(bh[j], BH + off);
            ldmat4(bl[j], BL + off);
        }
        #pragma unroll
        for (int s = 0; s < 2; s++) {
            uint32_t ah[4][4], al[4][4];
            #pragma unroll
            for (int i = 0; i < 4; i++) {
                uint32_t off = (uint32_t)((wr*64 + i*16 + (lane & 15)) * 144 + half*64 + s*32 + (lane >> 4) * 16);
                ldmat4(ah[i], AH + off);
                ldmat4(al[i], AL + off);
            }
            #pragma unroll
            for (int i = 0; i < 4; i++)
                #pragma unroll
                for (int j = 0; j < 4; j++) {
                    mma_bf16(acc[i][j], ah[i], &bh[j][s*2]);
                    mma_bf16(acc[i][j], ah[i], &bl[j][s*2]);
                    mma_bf16(acc[i][j], al[i], &bh[j][s*2]);
                }
        }
    }
}

// one k=64 chunk, CTA tile 128x64, warp tile 64x16
__device__ __forceinline__ void consume_128x64(
    uint32_t AH, uint32_t AL, uint32_t BH, uint32_t BL,
    int wr, int wc, int lane, float (&acc)[4][2][4]) {
    #pragma unroll
    for (int half = 0; half < 2; half++) {
        uint32_t bh[2][4], bl[2][4];
        #pragma unroll
        for (int j = 0; j < 2; j++) {
            uint32_t off = (uint32_t)((wc*16 + j*8 + (lane & 7)) * 144 + half*64 + ((lane >> 3) & 3) * 16);
            ldmat4(bh[j], BH + off);
            ldmat4(bl[j], BL + off);
        }
        #pragma unroll
        for (int s = 0; s < 2; s++) {
            #pragma unroll
            for (int i = 0; i < 4; i++) {
                uint32_t ah[4], al[4];
                uint32_t off = (uint32_t)((wr*64 + i*16 + (lane & 15)) * 144 + half*64 + s*32 + (lane >> 4) * 16);
                ldmat4(ah, AH + off);
                ldmat4(al, AL + off);
                #pragma unroll
                for (int j = 0; j < 2; j++) {
                    mma_bf16(acc[i][j], ah, &bh[j][s*2]);
                    mma_bf16(acc[i][j], ah, &bl[j][s*2]);
                    mma_bf16(acc[i][j], al, &bh[j][s*2]);
                }
            }
        }
    }
}

#define GBUF 73728

// ---------------------------------------------------------------------------
// prep: split x and the 4 weight matrices into bf16 hi/lo planes
// ---------------------------------------------------------------------------
__global__ __launch_bounds__(256) void prep_kernel(
    const float* __restrict__ x, const float* __restrict__ Wq,
    const float* __restrict__ Wk, const float* __restrict__ Wv,
    const float* __restrict__ Wp)
{
    const int y = blockIdx.y;
    const float* src;
    __nv_bfloat16 *dh, *dl;
    int n;
    if (y == 0) { src = x; dh = g_x_hi; dl = g_x_lo; n = 4096*768; }
    else {
        src = (y == 1) ? Wq : (y == 2) ? Wk : (y == 3) ? Wv : Wp;
        dh = g_w_hi + (size_t)(y-1)*589824;
        dl = g_w_lo + (size_t)(y-1)*589824;
        n = 589824;
    }
    int i4 = blockIdx.x * 256 + threadIdx.x;
    if (i4 * 4 >= n) return;
    float4 f = ((const float4*)src)[i4];
    uint2 hi, lo;
    split4(f, hi, lo);
    ((uint2*)dh)[i4] = hi;
    ((uint2*)dl)[i4] = lo;
}

// ---------------------------------------------------------------------------
// QKV projection (tensor): out = x @ W^T, M=4096 N=768 K=768, z selects q/k/v
// ---------------------------------------------------------------------------
__global__ __launch_bounds__(256, 1) void qkv_kernel()
{
    extern __shared__ char dsm[];
    const uint32_t sb = smem_u32(dsm);
    const int t = threadIdx.x, lane = t & 31, w = t >> 5, wr = w >> 2, wc = w & 3;
    const int m0 = blockIdx.y * 128, n0 = blockIdx.x * 128, z = blockIdx.z;
    float* out = (z == 0) ? g_q : (z == 1) ? g_k : g_v;

    const int row = t >> 1, hf = t & 1;
    const __nv_bfloat16* ah = g_x_hi + (size_t)(m0+row)*768 + hf*32;
    const __nv_bfloat16* al = g_x_lo + (size_t)(m0+row)*768 + hf*32;
    const __nv_bfloat16* bh = g_w_hi + (size_t)z*589824 + (size_t)(n0+row)*768 + hf*32;
    const __nv_bfloat16* bl = g_w_lo + (size_t)z*589824 + (size_t)(n0+row)*768 + hf*32;
    const uint32_t doff = (uint32_t)(row*144 + hf*64);

    float acc[4][4][4] = {};
    issue4(sb + doff, ah, al, bh, bl);
    for (int c = 0; c < 12; c++) {
        if (c + 1 < 12)
            issue4(sb + ((c+1)&1)*GBUF + doff, ah + (c+1)*64, al + (c+1)*64, bh + (c+1)*64, bl + (c+1)*64);
        if (c + 1 < 12) cp_wait1(); else cp_wait0();
        __syncthreads();
        uint32_t bb = sb + (c & 1)*GBUF;
        consume_128x128(bb, bb+18432, bb+36864, bb+55296, wr, wc, lane, acc);
        __syncthreads();
    }
    const int r0 = lane >> 2, cp2 = (lane & 3)*2;
    #pragma unroll
    for (int i = 0; i < 4; i++) {
        int m = m0 + wr*64 + i*16 + r0;
        int b = m >> 11, tt = m & (Tt-1);
        #pragma unroll
        for (int j = 0; j < 4; j++) {
            int n = n0 + wc*32 + j*8 + cp2;
            int h = n >> 6, d = n & 63;
            size_t base = (((size_t)(b*Hh + h))*Tt + tt)*Dd + d;
            *(float2*)&out[base]          = make_float2(acc[i][j][0], acc[i][j][1]);
            *(float2*)&out[base + 8*Dd]   = make_float2(acc[i][j][2], acc[i][j][3]);
        }
    }
}

// ---------------------------------------------------------------------------
// rope tables + rope (fp32 q/k -> rotated, split to bf16 hi/lo planes)
// ---------------------------------------------------------------------------
__global__ __launch_bounds__(256) void rope_prep()
{
    int idx = blockIdx.x * 256 + threadIdx.x;
    if (idx >= Tt * 16) return;
    int t = idx >> 4, p = idx & 15;
    const float L2 = 0.41524101186092028f; // log2(10000)/32
    float f1 = exp2f(-(float)p * L2), f2 = exp2f(-(float)(p + 16) * L2);
    float s1, c1, s2, c2;
    sincosf((float)t * f1, &s1, &c1);
    sincosf((float)t * f2, &s2, &c2);
    float* r = g_rope + (size_t)t * 64;
    r[p] = c1; r[p + 16] = s1; r[p + 32] = c2; r[p + 48] = s2;
}

__global__ __launch_bounds__(256) void rope_kernel()
{
    int gidx = blockIdx.x * 256 + threadIdx.x;     // 2 threads per row
    if (gidx >= NBH * Tt * 2) return;
    int ri = gidx >> 1, hf = gidx & 1;
    int t = ri & (Tt - 1);
    const float* tab = g_rope + (size_t)t * 64;
    #pragma unroll
    for (int which = 0; which < 2; which++) {
        const float* src = ((which == 0) ? g_q : g_k) + (size_t)ri*64 + hf*32;
        __nv_bfloat16* dh = ((which == 0) ? g_q_hi : g_k_hi) + (size_t)ri*64 + hf*32;
        __nv_bfloat16* dl = ((which == 0) ? g_q_lo : g_k_lo) + (size_t)ri*64 + hf*32;
        float v[32];
        #pragma unroll
        for (int g = 0; g < 8; g++) *(float4*)&v[g*4] = ((const float4*)src)[g];
        if (hf == 0) {
            float o[32];
            #pragma unroll
            for (int p = 0; p < 16; p++) {
                o[p]      = v[p] * tab[p]      - v[p+16] * tab[p+16];
                o[p + 16] = v[p+16] * tab[p+32] + v[p]    * tab[p+48];
            }
            #pragma unroll
            for (int p = 0; p < 32; p++) v[p] = o[p];
        }
        #pragma unroll
        for (int g = 0; g < 8; g++) {
            uint2 hi, lo;
            split4(*(float4*)&v[g*4], hi, lo);
            ((uint2*)dh)[g] = hi;
            ((uint2*)dl)[g] = lo;
        }
    }
}

// ---------------------------------------------------------------------------
// v transpose + split: g_v[bh][t][d] -> g_vT_{hi,lo}[bh][d][t]
// ---------------------------------------------------------------------------
__global__ __launch_bounds__(256) void vT_kernel()
{
    __shared__ float tile[32][33];
    const int bh = blockIdx.z, t0 = blockIdx.x * 32, d0 = blockIdx.y * 32;
    const int tx = threadIdx.x & 31, ty = threadIdx.x >> 5;
    const float* src = g_v + ((size_t)bh * Tt + t0) * Dd + d0;
    #pragma unroll
    for (int r = 0; r < 32; r += 8) tile[ty + r][tx] = src[(size_t)(ty + r) * Dd + tx];
    __syncthreads();
    #pragma unroll
    for (int r = 0; r < 32; r += 8) {
        float v = tile[tx][ty + r];
        size_t o = ((size_t)bh * Dd + d0 + ty + r) * Tt + t0 + tx;
        __nv_bfloat16 h = __float2bfloat16(v);
        g_vT_hi[o] = h;
        g_vT_lo[o] = __float2bfloat16(v - __bfloat162float(h));
    }
}

// ---------------------------------------------------------------------------
// logits (tensor): att[m,n] = 0.125*q.k + rel_bias   (K=64, single chunk)
// ---------------------------------------------------------------------------
__global__ __launch_bounds__(256, 1) void logits_kernel(
    const float* __restrict__ rel_bias, float* __restrict__ att)
{
    const int kt = blockIdx.x, qt = blockIdx.y, bh = blockIdx.z;
    if (kt > qt) return;
    extern __shared__ char dsm[];
    __shared__ float bias_s[256];
    const uint32_t sb = smem_u32(dsm);
    const int t = threadIdx.x, lane = t & 31, w = t >> 5, wr = w >> 2, wc = w & 3;
    const int h = bh % Hh;
    const int dlo = (qt - kt) * 128 - 127;
    for (int i = t; i < 255; i += 256)
        bias_s[i] = __ldg(&rel_bias[(size_t)(dlo + i + Tt - 1) * Hh + h]);

    const int row = t >> 1, hf = t & 1;
    issue4(sb + (uint32_t)(row*144 + hf*64),
           g_q_hi + ((size_t)bh*Tt + qt*128 + row)*Dd + hf*32,
           g_q_lo + ((size_t)bh*Tt + qt*128 + row)*Dd + hf*32,
           g_k_hi + ((size_t)bh*Tt + kt*128 + row)*Dd + hf*32,
           g_k_lo + ((size_t)bh*Tt + kt*128 + row)*Dd + hf*32);
    cp_wait0();
    __syncthreads();
    float acc[4][4][4] = {};
    consume_128x128(sb, sb+18432, sb+36864, sb+55296, wr, wc, lane, acc);

    const int r0 = lane >> 2, cp2 = (lane & 3)*2;
    float* A = att + (size_t)bh * Tt * Tt;
    #pragma unroll
    for (int i = 0; i < 4; i++) {
        int mi = wr*64 + i*16 + r0;
        #pragma unroll
        for (int j = 0; j < 4; j++) {
            int ni = wc*32 + j*8 + cp2;
            float b0 = bias_s[mi - ni + 127],      b1 = bias_s[mi - ni + 126];
            float b2 = bias_s[mi + 8 - ni + 127],  b3 = bias_s[mi + 8 - ni + 126];
            size_t base = ((size_t)qt*128 + mi)*Tt + kt*128 + ni;
            *(float2*)&A[base]        = make_float2(acc[i][j][0]*0.125f + b0, acc[i][j][1]*0.125f + b1);
            *(float2*)&A[base + 8*Tt] = make_float2(acc[i][j][2]*0.125f + b2, acc[i][j][3]*0.125f + b3);
        }
    }
}

// ---------------------------------------------------------------------------
// row softmax in place, causal-trimmed, vectorized
// ---------------------------------------------------------------------------
__global__ __launch_bounds__(256) void softmax_kernel(float* __restrict__ att)
{
    const int row = blockIdx.x;
    const int m = row & (Tt - 1);
    const int L = m + 1;
    const int nL4 = (L + 3) >> 2;
    float4* A = (float4*)(att + (size_t)row * Tt);
    __shared__ float4 buf[Tt/4];
    __shared__ float red[8];
    const int tid = threadIdx.x;

    float mx = -1e30f;
    for (int j = tid; j < nL4; j += 256) {
        float4 v = A[j];
        int base = j * 4;
        if (base + 0 < L) mx = fmaxf(mx, v.x);
        if (base + 1 < L) mx = fmaxf(mx, v.y);
        if (base + 2 < L) mx = fmaxf(mx, v.z);
        if (base + 3 < L) mx = fmaxf(mx, v.w);
        buf[j] = v;
    }
    #pragma unroll
    for (int o = 16; o; o >>= 1) mx = fmaxf(mx, __shfl_xor_sync(0xffffffffu, mx, o));
    if ((tid & 31) == 0) red[tid >> 5] = mx;
    __syncthreads();
    mx = red[0];
    #pragma unroll
    for (int ww = 1; ww < 8; ww++) mx = fmaxf(mx, red[ww]);
    __syncthreads();

    float s = 0.f;
    for (int j = tid; j < nL4; j += 256) {
        float4 v = buf[j];
        int base = j * 4;
        v.x = (base + 0 < L) ? __expf(v.x - mx) : 0.f;
        v.y = (base + 1 < L) ? __expf(v.y - mx) : 0.f;
        v.z = (base + 2 < L) ? __expf(v.z - mx) : 0.f;
        v.w = (base + 3 < L) ? __expf(v.w - mx) : 0.f;
        s += v.x + v.y + v.z + v.w;
        buf[j] = v;
    }
    #pragma unroll
    for (int o = 16; o; o >>= 1) s += __shfl_xor_sync(0xffffffffu, s, o);
    if ((tid & 31) == 0) red[tid >> 5] = s;
    __syncthreads();
    s = red[0];
    #pragma unroll
    for (int ww = 1; ww < 8; ww++) s += red[ww];
    const float inv = 1.f / s;

    for (int j = tid; j < Tt/4; j += 256) {
        float4 e = (j < nL4) ? buf[j] : make_float4(0.f, 0.f, 0.f, 0.f);
        e.x *= inv; e.y *= inv; e.z *= inv; e.w *= inv;
        A[j] = e;
    }
}

// ---------------------------------------------------------------------------
// av (tensor): y = att @ v, att fp32 staged via cp.async + in-smem split
// smem: AF32 buf x2 (stride 272B rows), B bf16 buf x2, A tiles hi/lo (single)
// ---------------------------------------------------------------------------
#define AV_AF_STRIDE 34816
#define AV_B_BASE    69632
#define AV_B_STRIDE  18432
#define AV_TH        106496
#define AV_TL        124928
#define AV_SMEM      143360

__global__ __launch_bounds__(256, 1) void av_kernel(const float* __restrict__ att)
{
    extern __shared__ char dsm[];
    const uint32_t sb = smem_u32(dsm);
    const int mt = blockIdx.x, bh = blockIdx.y;
    const int t = threadIdx.x, lane = t & 31, w = t >> 5, wr = w >> 2, wc = w & 3;
    const float* As = att + (size_t)bh * Tt * Tt;

    const int row = t >> 1, hf = t & 1;
    const int br = t >> 2, bq = t & 3;
    const int nk = (mt + 1) * 2;

    float acc[4][2][4] = {};

    // issue chunk 0
    {
        const float* asrc = As + ((size_t)(mt*128 + row))*Tt + hf*32;
        uint32_t afd = sb + (uint32_t)(row*272 + hf*128);
        #pragma unroll
        for (int j = 0; j < 8; j++) cpa16(afd + j*16, asrc + j*4);
        #pragma unroll
        for (int s2 = 0; s2 < 4; s2++) {
            int idx = bq*4 + s2, pl = idx >> 3, ko = idx & 7;
            const __nv_bfloat16* src = (pl ? g_vT_lo : g_vT_hi) + ((size_t)bh*Dd + br)*Tt + ko*8;
            cpa16(sb + AV_B_BASE + pl*9216 + (uint32_t)(br*144 + ko*16), src);
        }
        cp_commit();
    }

    for (int c = 0; c < nk; c++) {
        if (c + 1 < nk) {
            const float* asrc = As + ((size_t)(mt*128 + row))*Tt + (c+1)*64 + hf*32;
            uint32_t afd = sb + ((c+1)&1)*AV_AF_STRIDE + (uint32_t)(row*272 + hf*128);
            #pragma unroll
            for (int j = 0; j < 8; j++) cpa16(afd + j*16, asrc + j*4);
            #pragma unroll
            for (int s2 = 0; s2 < 4; s2++) {
                int idx = bq*4 + s2, pl = idx >> 3, ko = idx & 7;
                const __nv_bfloat16* src = (pl ? g_vT_lo : g_vT_hi) + ((size_t)bh*Dd + br)*Tt + (c+1)*64 + ko*8;
                cpa16(sb + AV_B_BASE + ((c+1)&1)*AV_B_STRIDE + pl*9216 + (uint32_t)(br*144 + ko*16), src);
            }
            cp_commit();
        }
        if (c + 1 < nk) cp_wait1(); else cp_wait0();
        __syncthreads();
        // convert fp32 A chunk -> hi/lo tiles
        {
            const char* afb = dsm + (c & 1)*AV_AF_STRIDE + row*272 + hf*128;
            char* th = dsm + AV_TH + row*144 + hf*64;
            char* tl = dsm + AV_TL + row*144 + hf*64;
            #pragma unroll
            for (int j = 0; j < 4; j++) {
                float4 f0 = *(const float4*)(afb + j*32);
                float4 f1 = *(const float4*)(afb + j*32 + 16);
                uint2 h0, l0, h1, l1;
                split4(f0, h0, l0);
                split4(f1, h1, l1);
                *(uint4*)(th + j*16) = make_uint4(h0.x, h0.y, h1.x, h1.y);
                *(uint4*)(tl + j*16) = make_uint4(l0.x, l0.y, l1.x, l1.y);
            }
        }
        __syncthreads();
        uint32_t bbuf = sb + AV_B_BASE + (c & 1)*AV_B_STRIDE;
        consume_128x64(sb + AV_TH, sb + AV_TL, bbuf, bbuf + 9216, wr, wc, lane, acc);
        __syncthreads();
    }

    const int r0 = lane >> 2, cp2 = (lane & 3)*2;
    #pragma unroll
    for (int i = 0; i < 4; i++) {
        int m = mt*128 + wr*64 + i*16 + r0;
        #pragma unroll
        for (int j = 0; j < 2; j++) {
            int n = wc*16 + j*8 + cp2;
            size_t idx = ((size_t)bh*Tt + m)*Dd + n;
            uint32_t hi, lo;
            split2u(acc[i][j][0], acc[i][j][1], hi, lo);
            *(uint32_t*)&g_y_hi[idx] = hi;
            *(uint32_t*)&g_y_lo[idx] = lo;
            split2u(acc[i][j][2], acc[i][j][3], hi, lo);
            *(uint32_t*)&g_y_hi[idx + 8*Dd] = hi;
            *(uint32_t*)&g_y_lo[idx + 8*Dd] = lo;
        }
    }
}

// ---------------------------------------------------------------------------
// output projection (tensor): y = yatt @ Wp^T + bp, M=4096 N=768 K=768
// ---------------------------------------------------------------------------
__global__ __launch_bounds__(256, 1) void proj_kernel(
    const float* __restrict__ bp, float* __restrict__ y)
{
    extern __shared__ char dsm[];
    const uint32_t sb = smem_u32(dsm);
    const int t = threadIdx.x, lane = t & 31, w = t >> 5, wr = w >> 2, wc = w & 3;
    const int m0 = blockIdx.y * 128, n0 = blockIdx.x * 128;

    const int row = t >> 1, hf = t & 1;
    const int mrow = m0 + row, b_ = mrow >> 11, t_ = mrow & (Tt - 1);
    const __nv_bfloat16* bh = g_w_hi + (size_t)3*589824 + (size_t)(n0+row)*768 + hf*32;
    const __nv_bfloat16* bl = g_w_lo + (size_t)3*589824 + (size_t)(n0+row)*768 + hf*32;
    const uint32_t doff = (uint32_t)(row*144 + hf*64);

    float acc[4][4][4] = {};
    issue4(sb + doff,
           g_y_hi + (((size_t)(b_*Hh + 0))*Tt + t_)*Dd + hf*32,
           g_y_lo + (((size_t)(b_*Hh + 0))*Tt + t_)*Dd + hf*32,
           bh, bl);
    for (int c = 0; c < 12; c++) {
        if (c + 1 < 12)
            issue4(sb + ((c+1)&1)*GBUF + doff,
                   g_y_hi + (((size_t)(b_*Hh + c+1))*Tt + t_)*Dd + hf*32,
                   g_y_lo + (((size_t)(b_*Hh + c+1))*Tt + t_)*Dd + hf*32,
                   bh + (c+1)*64, bl + (c+1)*64);
        if (c + 1 < 12) cp_wait1(); else cp_wait0();
        __syncthreads();
        uint32_t bb = sb + (c & 1)*GBUF;
        consume_128x128(bb, bb+18432, bb+36864, bb+55296, wr, wc, lane, acc);
        __syncthreads();
    }
    const int r0 = lane >> 2, cp2 = (lane & 3)*2;
    #pragma unroll
    for (int i = 0; i < 4; i++) {
        int m = m0 + wr*64 + i*16 + r0;
        #pragma unroll
        for (int j = 0; j < 4; j++) {
            int n = n0 + wc*32 + j*8 + cp2;
            float2 bv = *(const float2*)&bp[n];
            *(float2*)&y[(size_t)m*Cc + n] =
                make_float2(acc[i][j][0] + bv.x, acc[i][j][1] + bv.y);
            *(float2*)&y[(size_t)(m+8)*Cc + n] =
                make_float2(acc[i][j][2] + bv.x, acc[i][j][3] + bv.y);
        }
    }
}

// ---------------------------------------------------------------------------
extern "C" void kernel_launch(void* const* d_in, const int* in_sizes, int n_in,
                              void* d_out, int out_size)
{
    (void)in_sizes; (void)n_in; (void)out_size;
    const float* x  = (const float*)d_in[0];
    const float* Wq = (const float*)d_in[1];
    const float* Wk = (const float*)d_in[2];
    const float* Wv = (const float*)d_in[3];
    const float* Wp = (const float*)d_in[4];
    const float* bp = (const float*)d_in[5];
    const float* rb = (const float*)d_in[6];
    float* y   = (float*)d_out;
    float* att = y + (size_t)Bb * Tt * Cc;

    static int inited = 0;
    if (!inited) {
        cudaFuncSetAttribute(qkv_kernel,    cudaFuncAttributeMaxDynamicSharedMemorySize, 2*GBUF);
        cudaFuncSetAttribute(logits_kernel, cudaFuncAttributeMaxDynamicSharedMemorySize, GBUF);
        cudaFuncSetAttribute(av_kernel,     cudaFuncAttributeMaxDynamicSharedMemorySize, AV_SMEM);
        cudaFuncSetAttribute(proj_kernel,   cudaFuncAttributeMaxDynamicSharedMemorySize, 2*GBUF);
        inited = 1;
    }

    prep_kernel   <<<dim3(3072, 5), 256>>>(x, Wq, Wk, Wv, Wp);
    qkv_kernel    <<<dim3(6, 32, 3), 256, 2*GBUF>>>();
    rope_prep     <<<128, 256>>>();
    rope_kernel   <<<(NBH*Tt*2 + 255)/256, 256>>>();
    vT_kernel     <<<dim3(64, 2, NBH), 256>>>();
    logits_kernel <<<dim3(16, 16, NBH), 256, GBUF>>>(rb, att);
    softmax_kernel<<<NBH*Tt, 256>>>(att);
    av_kernel     <<<dim3(16, NBH), 256, AV_SMEM>>>(att);
    proj_kernel   <<<dim3(6, 32), 256, 2*GBUF>>>(bp, y);
}

// round 4
// speedup vs baseline: 2.0682x; 1.0782x over previous
#include <cuda_runtime.h>
#include <cuda_bf16.h>
#include <math.h>
#include <stdint.h>

#define Bb 2
#define Tt 2048
#define Cc 768
#define Hh 12
#define Dd 64
#define NBH (Bb*Hh)

// ---------------- scratch (device globals; no runtime allocation) ----------
__device__ float g_q[(size_t)NBH*Tt*Dd];
__device__ float g_k[(size_t)NBH*Tt*Dd];
__device__ float g_v[(size_t)NBH*Tt*Dd];
__device__ __nv_bfloat16 g_x_hi[(size_t)4096*768];
__device__ __nv_bfloat16 g_x_lo[(size_t)4096*768];
__device__ __nv_bfloat16 g_w_hi[(size_t)4*768*768];
__device__ __nv_bfloat16 g_w_lo[(size_t)4*768*768];
__device__ __nv_bfloat16 g_q_hi[(size_t)NBH*Tt*Dd];
__device__ __nv_bfloat16 g_q_lo[(size_t)NBH*Tt*Dd];
__device__ __nv_bfloat16 g_k_hi[(size_t)NBH*Tt*Dd];
__device__ __nv_bfloat16 g_k_lo[(size_t)NBH*Tt*Dd];
__device__ __nv_bfloat16 g_vT_hi[(size_t)NBH*Dd*Tt];
__device__ __nv_bfloat16 g_vT_lo[(size_t)NBH*Dd*Tt];
__device__ __nv_bfloat16 g_y_hi[(size_t)NBH*Tt*Dd];
__device__ __nv_bfloat16 g_y_lo[(size_t)NBH*Tt*Dd];
__device__ float g_rope[(size_t)Tt*64];

// ---------------- helpers ---------------------------------------------------
__device__ __forceinline__ uint32_t smem_u32(const void* p) {
    uint32_t a;
    asm("{ .reg .u64 t; cvta.to.shared.u64 t, %1; cvt.u32.u64 %0, t; }" : "=r"(a) : "l"(p));
    return a;
}
__device__ __forceinline__ void cpa16(uint32_t d, const void* s) {
    asm volatile("cp.async.cg.shared.global [%0], [%1], 16;" :: "r"(d), "l"(s));
}
__device__ __forceinline__ void cp_commit() { asm volatile("cp.async.commit_group;" ::: "memory"); }
__device__ __forceinline__ void cp_wait0()  { asm volatile("cp.async.wait_group 0;" ::: "memory"); }
__device__ __forceinline__ void cp_wait1()  { asm volatile("cp.async.wait_group 1;" ::: "memory"); }
__device__ __forceinline__ void ldmat4(uint32_t* r, uint32_t a) {
    asm volatile("ldmatrix.sync.aligned.m8n8.x4.shared.b16 {%0,%1,%2,%3}, [%4];"
                 : "=r"(r[0]), "=r"(r[1]), "=r"(r[2]), "=r"(r[3]) : "r"(a));
}
__device__ __forceinline__ void mma_bf16(float* c, const uint32_t* a, const uint32_t* b) {
    asm volatile("mma.sync.aligned.m16n8k16.row.col.f32.bf16.bf16.f32 "
                 "{%0,%1,%2,%3}, {%4,%5,%6,%7}, {%8,%9}, {%0,%1,%2,%3};"
                 : "+f"(c[0]), "+f"(c[1]), "+f"(c[2]), "+f"(c[3])
                 : "r"(a[0]), "r"(a[1]), "r"(a[2]), "r"(a[3]), "r"(b[0]), "r"(b[1]));
}
__device__ __forceinline__ uint32_t packbf2(float a, float b) {
    __nv_bfloat162 t = __floats2bfloat162_rn(a, b);
    return reinterpret_cast<uint32_t&>(t);
}
__device__ __forceinline__ void split2u(float a, float b, uint32_t& hi, uint32_t& lo) {
    float ah = __bfloat162float(__float2bfloat16(a));
    float bh = __bfloat162float(__float2bfloat16(b));
    hi = packbf2(ah, bh);
    lo = packbf2(a - ah, b - bh);
}
__device__ __forceinline__ void split4(float4 f, uint2& hi, uint2& lo) {
    split2u(f.x, f.y, hi.x, lo.x);
    split2u(f.z, f.w, hi.y, lo.y);
}

// cp.async issue: A-hi/A-lo/B-hi/B-lo tiles, 4x16B per plane per thread.
// tile row stride = 144 bytes, plane stride 18432 bytes.
__device__ __forceinline__ void issue4(uint32_t dbase,
    const __nv_bfloat16* s0, const __nv_bfloat16* s1,
    const __nv_bfloat16* s2, const __nv_bfloat16* s3) {
    #pragma unroll
    for (int j = 0; j < 4; j++) {
        cpa16(dbase + 0u*18432u + j*16, s0 + j*8);
        cpa16(dbase + 1u*18432u + j*16, s1 + j*8);
        cpa16(dbase + 2u*18432u + j*16, s2 + j*8);
        cpa16(dbase + 3u*18432u + j*16, s3 + j*8);
    }
    cp_commit();
}

// one k=64 chunk, CTA tile 128x128, warp tile 64x32
__device__ __forceinline__ void consume_128x128(
    uint32_t AH, uint32_t AL, uint32_t BH, uint32_t BL,
    int wr, int wc, int lane, float (&acc)[4][4][4]) {
    #pragma unroll
    for (int half = 0; half < 2; half++) {
        uint32_t bh[4][4], bl[4][4];
        #pragma unroll
        for (int j = 0; j < 4; j++) {
            uint32_t off = (uint32_t)((wc*32 + j*8 + (lane & 7)) * 144 + half*64 + ((lane >> 3) & 3) * 16);
            ldmat4(bh[j], BH + off);
            ldmat4(bl[j], BL + off);
        }
        #pragma unroll
        for (int s = 0; s < 2; s++) {
            uint32_t ah[4][4], al[4][4];
            #pragma unroll
            for (int i = 0; i < 4; i++) {
                uint32_t off = (uint32_t)((wr*64 + i*16 + (lane & 15)) * 144 + half*64 + s*32 + (lane >> 4) * 16);
                ldmat4(ah[i], AH + off);
                ldmat4(al[i], AL + off);
            }
            #pragma unroll
            for (int i = 0; i < 4; i++)
                #pragma unroll
                for (int j = 0; j < 4; j++) {
                    mma_bf16(acc[i][j], ah[i], &bh[j][s*2]);
                    mma_bf16(acc[i][j], ah[i], &bl[j][s*2]);
                    mma_bf16(acc[i][j], al[i], &bh[j][s*2]);
                }
        }
    }
}

// one k=64 chunk, CTA tile 128x64, warp tile 64x16
__device__ __forceinline__ void consume_128x64(
    uint32_t AH, uint32_t AL, uint32_t BH, uint32_t BL,
    int wr, int wc, int lane, float (&acc)[4][2][4]) {
    #pragma unroll
    for (int half = 0; half < 2; half++) {
        uint32_t bh[2][4], bl[2][4];
        #pragma unroll
        for (int j = 0; j < 2; j++) {
            uint32_t off = (uint32_t)((wc*16 + j*8 + (lane & 7)) * 144 + half*64 + ((lane >> 3) & 3) * 16);
            ldmat4(bh[j], BH + off);
            ldmat4(bl[j], BL + off);
        }
        #pragma unroll
        for (int s = 0; s < 2; s++) {
            #pragma unroll
            for (int i = 0; i < 4; i++) {
                uint32_t ah[4], al[4];
                uint32_t off = (uint32_t)((wr*64 + i*16 + (lane & 15)) * 144 + half*64 + s*32 + (lane >> 4) * 16);
                ldmat4(ah, AH + off);
                ldmat4(al, AL + off);
                #pragma unroll
                for (int j = 0; j < 2; j++) {
                    mma_bf16(acc[i][j], ah, &bh[j][s*2]);
                    mma_bf16(acc[i][j], ah, &bl[j][s*2]);
                    mma_bf16(acc[i][j], al, &bh[j][s*2]);
                }
            }
        }
    }
}

#define GBUF 73728

// ---------------------------------------------------------------------------
// prep: split x and the 4 weight matrices into bf16 hi/lo planes
// ---------------------------------------------------------------------------
__global__ __launch_bounds__(256) void prep_kernel(
    const float* __restrict__ x, const float* __restrict__ Wq,
    const float* __restrict__ Wk, const float* __restrict__ Wv,
    const float* __restrict__ Wp)
{
    const int y = blockIdx.y;
    const float* src;
    __nv_bfloat16 *dh, *dl;
    int n;
    if (y == 0) { src = x; dh = g_x_hi; dl = g_x_lo; n = 4096*768; }
    else {
        src = (y == 1) ? Wq : (y == 2) ? Wk : (y == 3) ? Wv : Wp;
        dh = g_w_hi + (size_t)(y-1)*589824;
        dl = g_w_lo + (size_t)(y-1)*589824;
        n = 589824;
    }
    int i4 = blockIdx.x * 256 + threadIdx.x;
    if (i4 * 4 >= n) return;
    float4 f = ((const float4*)src)[i4];
    uint2 hi, lo;
    split4(f, hi, lo);
    ((uint2*)dh)[i4] = hi;
    ((uint2*)dl)[i4] = lo;
}

// ---------------------------------------------------------------------------
// QKV projection (tensor): out = x @ W^T, M=4096 N=768 K=768, z selects q/k/v
// ---------------------------------------------------------------------------
__global__ __launch_bounds__(256, 1) void qkv_kernel()
{
    extern __shared__ char dsm[];
    const uint32_t sb = smem_u32(dsm);
    const int t = threadIdx.x, lane = t & 31, w = t >> 5, wr = w >> 2, wc = w & 3;
    const int m0 = blockIdx.y * 128, n0 = blockIdx.x * 128, z = blockIdx.z;
    float* out = (z == 0) ? g_q : (z == 1) ? g_k : g_v;

    const int row = t >> 1, hf = t & 1;
    const __nv_bfloat16* ah = g_x_hi + (size_t)(m0+row)*768 + hf*32;
    const __nv_bfloat16* al = g_x_lo + (size_t)(m0+row)*768 + hf*32;
    const __nv_bfloat16* bh = g_w_hi + (size_t)z*589824 + (size_t)(n0+row)*768 + hf*32;
    const __nv_bfloat16* bl = g_w_lo + (size_t)z*589824 + (size_t)(n0+row)*768 + hf*32;
    const uint32_t doff = (uint32_t)(row*144 + hf*64);

    float acc[4][4][4] = {};
    issue4(sb + doff, ah, al, bh, bl);
    for (int c = 0; c < 12; c++) {
        if (c + 1 < 12)
            issue4(sb + ((c+1)&1)*GBUF + doff, ah + (c+1)*64, al + (c+1)*64, bh + (c+1)*64, bl + (c+1)*64);
        if (c + 1 < 12) cp_wait1(); else cp_wait0();
        __syncthreads();
        uint32_t bb = sb + (c & 1)*GBUF;
        consume_128x128(bb, bb+18432, bb+36864, bb+55296, wr, wc, lane, acc);
        __syncthreads();
    }
    const int r0 = lane >> 2, cp2 = (lane & 3)*2;
    #pragma unroll
    for (int i = 0; i < 4; i++) {
        int m = m0 + wr*64 + i*16 + r0;
        int b = m >> 11, tt = m & (Tt-1);
        #pragma unroll
        for (int j = 0; j < 4; j++) {
            int n = n0 + wc*32 + j*8 + cp2;
            int h = n >> 6, d = n & 63;
            size_t base = (((size_t)(b*Hh + h))*Tt + tt)*Dd + d;
            *(float2*)&out[base]          = make_float2(acc[i][j][0], acc[i][j][1]);
            *(float2*)&out[base + 8*Dd]   = make_float2(acc[i][j][2], acc[i][j][3]);
        }
    }
}

// ---------------------------------------------------------------------------
// rope tables
// ---------------------------------------------------------------------------
__global__ __launch_bounds__(256) void rope_prep()
{
    int idx = blockIdx.x * 256 + threadIdx.x;
    if (idx >= Tt * 16) return;
    int t = idx >> 4, p = idx & 15;
    const float L2 = 0.41524101186092028f; // log2(10000)/32
    float f1 = exp2f(-(float)p * L2), f2 = exp2f(-(float)(p + 16) * L2);
    float s1, c1, s2, c2;
    sincosf((float)t * f1, &s1, &c1);
    sincosf((float)t * f2, &s2, &c2);
    float* r = g_rope + (size_t)t * 64;
    r[p] = c1; r[p + 16] = s1; r[p + 32] = c2; r[p + 48] = s2;
}

// ---------------------------------------------------------------------------
// rope: 8 threads/row, shfl pair exchange, coalesced. q,k fp32 -> hi/lo bf16
// ---------------------------------------------------------------------------
__global__ __launch_bounds__(256) void rope_kernel()
{
    const int gid = blockIdx.x * 256 + threadIdx.x;   // NBH*Tt*8 threads exactly
    const int j = gid & 7;
    const int ri = gid >> 3;
    const int t = ri & (Tt - 1);
    const float* tab = g_rope + (size_t)t * 64;

    float vq[8], vk[8];
    *(float4*)&vq[0] = *(const float4*)(g_q + (size_t)ri*64 + j*8);
    *(float4*)&vq[4] = *(const float4*)(g_q + (size_t)ri*64 + j*8 + 4);
    *(float4*)&vk[0] = *(const float4*)(g_k + (size_t)ri*64 + j*8);
    *(float4*)&vk[4] = *(const float4*)(g_k + (size_t)ri*64 + j*8 + 4);

    float pq[8], pk[8];
    #pragma unroll
    for (int e = 0; e < 8; e++) {
        pq[e] = __shfl_xor_sync(0xffffffffu, vq[e], 2);
        pk[e] = __shfl_xor_sync(0xffffffffu, vk[e], 2);
    }
    if (j < 2) {                 // p = j*8+e < 16
        #pragma unroll
        for (int e = 0; e < 8; e++) {
            int p = j*8 + e;
            float cs = tab[p], sn = tab[16 + p];
            vq[e] = vq[e]*cs - pq[e]*sn;
            vk[e] = vk[e]*cs - pk[e]*sn;
        }
    } else if (j < 4) {          // p = j*8+e in [16,32)
        #pragma unroll
        for (int e = 0; e < 8; e++) {
            int p = j*8 + e;
            float cs = tab[p + 16], sn = tab[p + 32];
            vq[e] = vq[e]*cs + pq[e]*sn;
            vk[e] = vk[e]*cs + pk[e]*sn;
        }
    }
    // split + store (uint4 = 8 bf16)
    uint2 h0, l0, h1, l1;
    split4(*(float4*)&vq[0], h0, l0);
    split4(*(float4*)&vq[4], h1, l1);
    *(uint4*)(g_q_hi + (size_t)ri*64 + j*8) = make_uint4(h0.x, h0.y, h1.x, h1.y);
    *(uint4*)(g_q_lo + (size_t)ri*64 + j*8) = make_uint4(l0.x, l0.y, l1.x, l1.y);
    split4(*(float4*)&vk[0], h0, l0);
    split4(*(float4*)&vk[4], h1, l1);
    *(uint4*)(g_k_hi + (size_t)ri*64 + j*8) = make_uint4(h0.x, h0.y, h1.x, h1.y);
    *(uint4*)(g_k_lo + (size_t)ri*64 + j*8) = make_uint4(l0.x, l0.y, l1.x, l1.y);
}

// ---------------------------------------------------------------------------
// v transpose + split: g_v[bh][t][d] -> g_vT_{hi,lo}[bh][d][t]
// ---------------------------------------------------------------------------
__global__ __launch_bounds__(256) void vT_kernel()
{
    __shared__ float tile[32][33];
    const int bh = blockIdx.z, t0 = blockIdx.x * 32, d0 = blockIdx.y * 32;
    const int tx = threadIdx.x & 31, ty = threadIdx.x >> 5;
    const float* src = g_v + ((size_t)bh * Tt + t0) * Dd + d0;
    #pragma unroll
    for (int r = 0; r < 32; r += 8) tile[ty + r][tx] = src[(size_t)(ty + r) * Dd + tx];
    __syncthreads();
    #pragma unroll
    for (int r = 0; r < 32; r += 8) {
        float v = tile[tx][ty + r];
        size_t o = ((size_t)bh * Dd + d0 + ty + r) * Tt + t0 + tx;
        __nv_bfloat16 h = __float2bfloat16(v);
        g_vT_hi[o] = h;
        g_vT_lo[o] = __float2bfloat16(v - __bfloat162float(h));
    }
}

// ---------------------------------------------------------------------------
// logits (tensor): att[m,n] = 0.125*q.k + rel_bias. occupancy 2, heavy-first.
// ---------------------------------------------------------------------------
__global__ __launch_bounds__(256, 2) void logits_kernel(
    const float* __restrict__ rel_bias, float* __restrict__ att)
{
    const int kt = blockIdx.x, qt = 15 - blockIdx.y, bh = blockIdx.z;
    if (kt > qt) return;
    extern __shared__ char dsm[];
    __shared__ float bias_s[256];
    const uint32_t sb = smem_u32(dsm);
    const int t = threadIdx.x, lane = t & 31, w = t >> 5, wr = w >> 2, wc = w & 3;
    const int h = bh % Hh;
    const int dlo = (qt - kt) * 128 - 127;
    for (int i = t; i < 255; i += 256)
        bias_s[i] = __ldg(&rel_bias[(size_t)(dlo + i + Tt - 1) * Hh + h]);

    const int row = t >> 1, hf = t & 1;
    issue4(sb + (uint32_t)(row*144 + hf*64),
           g_q_hi + ((size_t)bh*Tt + qt*128 + row)*Dd + hf*32,
           g_q_lo + ((size_t)bh*Tt + qt*128 + row)*Dd + hf*32,
           g_k_hi + ((size_t)bh*Tt + kt*128 + row)*Dd + hf*32,
           g_k_lo + ((size_t)bh*Tt + kt*128 + row)*Dd + hf*32);
    cp_wait0();
    __syncthreads();
    float acc[4][4][4] = {};
    consume_128x128(sb, sb+18432, sb+36864, sb+55296, wr, wc, lane, acc);

    const int r0 = lane >> 2, cp2 = (lane & 3)*2;
    float* A = att + (size_t)bh * Tt * Tt;
    #pragma unroll
    for (int i = 0; i < 4; i++) {
        int mi = wr*64 + i*16 + r0;
        #pragma unroll
        for (int j = 0; j < 4; j++) {
            int ni = wc*32 + j*8 + cp2;
            float b0 = bias_s[mi - ni + 127],      b1 = bias_s[mi - ni + 126];
            float b2 = bias_s[mi + 8 - ni + 127],  b3 = bias_s[mi + 8 - ni + 126];
            size_t base = ((size_t)qt*128 + mi)*Tt + kt*128 + ni;
            *(float2*)&A[base]        = make_float2(acc[i][j][0]*0.125f + b0, acc[i][j][1]*0.125f + b1);
            *(float2*)&A[base + 8*Tt] = make_float2(acc[i][j][2]*0.125f + b2, acc[i][j][3]*0.125f + b3);
        }
    }
}

// ---------------------------------------------------------------------------
// row softmax in place, causal-trimmed, vectorized
// ---------------------------------------------------------------------------
__global__ __launch_bounds__(256) void softmax_kernel(float* __restrict__ att)
{
    const int row = blockIdx.x;
    const int m = row & (Tt - 1);
    const int L = m + 1;
    const int nL4 = (L + 3) >> 2;
    float4* A = (float4*)(att + (size_t)row * Tt);
    __shared__ float4 buf[Tt/4];
    __shared__ float red[8];
    const int tid = threadIdx.x;

    float mx = -1e30f;
    for (int j = tid; j < nL4; j += 256) {
        float4 v = A[j];
        int base = j * 4;
        if (base + 0 < L) mx = fmaxf(mx, v.x);
        if (base + 1 < L) mx = fmaxf(mx, v.y);
        if (base + 2 < L) mx = fmaxf(mx, v.z);
        if (base + 3 < L) mx = fmaxf(mx, v.w);
        buf[j] = v;
    }
    #pragma unroll
    for (int o = 16; o; o >>= 1) mx = fmaxf(mx, __shfl_xor_sync(0xffffffffu, mx, o));
    if ((tid & 31) == 0) red[tid >> 5] = mx;
    __syncthreads();
    mx = red[0];
    #pragma unroll
    for (int ww = 1; ww < 8; ww++) mx = fmaxf(mx, red[ww]);
    __syncthreads();

    float s = 0.f;
    for (int j = tid; j < nL4; j += 256) {
        float4 v = buf[j];
        int base = j * 4;
        v.x = (base + 0 < L) ? __expf(v.x - mx) : 0.f;
        v.y = (base + 1 < L) ? __expf(v.y - mx) : 0.f;
        v.z = (base + 2 < L) ? __expf(v.z - mx) : 0.f;
        v.w = (base + 3 < L) ? __expf(v.w - mx) : 0.f;
        s += v.x + v.y + v.z + v.w;
        buf[j] = v;
    }
    #pragma unroll
    for (int o = 16; o; o >>= 1) s += __shfl_xor_sync(0xffffffffu, s, o);
    if ((tid & 31) == 0) red[tid >> 5] = s;
    __syncthreads();
    s = red[0];
    #pragma unroll
    for (int ww = 1; ww < 8; ww++) s += red[ww];
    const float inv = 1.f / s;

    for (int j = tid; j < Tt/4; j += 256) {
        float4 e = (j < nL4) ? buf[j] : make_float4(0.f, 0.f, 0.f, 0.f);
        e.x *= inv; e.y *= inv; e.z *= inv; e.w *= inv;
        A[j] = e;
    }
}

// ---------------------------------------------------------------------------
// av (tensor): y = att @ v. att chunk prefetched into REGISTERS (LDG),
// split in regs, STS into double-buffered hi/lo tiles. 2 CTAs/SM.
// smem: A tiles 2x(hi 18432 + lo 18432) = 73728, B 2x(9216*2) = 36864.
// ---------------------------------------------------------------------------
#define AV2_B_BASE 73728u
#define AV2_SMEM   110592

__global__ __launch_bounds__(256, 2) void av_kernel(const float* __restrict__ att)
{
    extern __shared__ char dsm[];
    const uint32_t sb = smem_u32(dsm);
    const int mt = 15 - blockIdx.x, bh = blockIdx.y;
    const int t = threadIdx.x, lane = t & 31, w = t >> 5, wr = w >> 2, wc = w & 3;
    const float* As = att + (size_t)bh * Tt * Tt;

    const int row = t >> 1, hf = t & 1;      // A staging: 2 threads/row
    const int br = t >> 2, bq = t & 3;       // B staging: 4 threads/row
    const int nk = (mt + 1) * 2;

    float acc[4][2][4] = {};
    float4 ap[8];

    // ---- prologue: chunk 0 ----
    {
        const float* asrc = As + ((size_t)(mt*128 + row))*Tt + hf*32;
        #pragma unroll
        for (int i = 0; i < 8; i++) ap[i] = __ldg((const float4*)asrc + i);
        #pragma unroll
        for (int pl = 0; pl < 2; pl++) {
            const __nv_bfloat16* src = (pl ? g_vT_lo : g_vT_hi) + ((size_t)bh*Dd + br)*Tt + bq*16;
            uint32_t dst = sb + AV2_B_BASE + pl*9216u + (uint32_t)(br*144 + bq*32);
            cpa16(dst, src);
            cpa16(dst + 16, src + 8);
        }
        cp_commit();
        // split regs -> tiles buf0
        char* th = dsm + row*144 + hf*64;
        char* tl = th + 18432;
        #pragma unroll
        for (int g = 0; g < 4; g++) {
            uint2 h0, l0, h1, l1;
            split4(ap[2*g],   h0, l0);
            split4(ap[2*g+1], h1, l1);
            *(uint4*)(th + g*16) = make_uint4(h0.x, h0.y, h1.x, h1.y);
            *(uint4*)(tl + g*16) = make_uint4(l0.x, l0.y, l1.x, l1.y);
        }
    }

    for (int c = 0; c < nk; c++) {
        if (c + 1 < nk) {
            // prefetch B(c+1) via cp.async, A(c+1) via LDG into regs
            #pragma unroll
            for (int pl = 0; pl < 2; pl++) {
                const __nv_bfloat16* src = (pl ? g_vT_lo : g_vT_hi) + ((size_t)bh*Dd + br)*Tt + (c+1)*64 + bq*16;
                uint32_t dst = sb + AV2_B_BASE + ((c+1)&1)*18432u + pl*9216u + (uint32_t)(br*144 + bq*32);
                cpa16(dst, src);
                cpa16(dst + 16, src + 8);
            }
            cp_commit();
            const float* asrc = As + ((size_t)(mt*128 + row))*Tt + (c+1)*64 + hf*32;
            #pragma unroll
            for (int i = 0; i < 8; i++) ap[i] = __ldg((const float4*)asrc + i);
        }
        if (c + 1 < nk) cp_wait1(); else cp_wait0();
        __syncthreads();
        uint32_t abuf = sb + (c & 1)*36864u;
        uint32_t bbuf = sb + AV2_B_BASE + (c & 1)*18432u;
        consume_128x64(abuf, abuf + 18432, bbuf, bbuf + 9216, wr, wc, lane, acc);
        if (c + 1 < nk) {
            char* th = dsm + ((c+1)&1)*36864 + row*144 + hf*64;
            char* tl = th + 18432;
            #pragma unroll
            for (int g = 0; g < 4; g++) {
                uint2 h0, l0, h1, l1;
                split4(ap[2*g],   h0, l0);
                split4(ap[2*g+1], h1, l1);
                *(uint4*)(th + g*16) = make_uint4(h0.x, h0.y, h1.x, h1.y);
                *(uint4*)(tl + g*16) = make_uint4(l0.x, l0.y, l1.x, l1.y);
            }
        }
        __syncthreads();
    }

    const int r0 = lane >> 2, cp2 = (lane & 3)*2;
    #pragma unroll
    for (int i = 0; i < 4; i++) {
        int m = mt*128 + wr*64 + i*16 + r0;
        #pragma unroll
        for (int j = 0; j < 2; j++) {
            int n = wc*16 + j*8 + cp2;
            size_t idx = ((size_t)bh*Tt + m)*Dd + n;
            uint32_t hi, lo;
            split2u(acc[i][j][0], acc[i][j][1], hi, lo);
            *(uint32_t*)&g_y_hi[idx] = hi;
            *(uint32_t*)&g_y_lo[idx] = lo;
            split2u(acc[i][j][2], acc[i][j][3], hi, lo);
            *(uint32_t*)&g_y_hi[idx + 8*Dd] = hi;
            *(uint32_t*)&g_y_lo[idx + 8*Dd] = lo;
        }
    }
}

// ---------------------------------------------------------------------------
// output projection (tensor): y = yatt @ Wp^T + bp, M=4096 N=768 K=768
// ---------------------------------------------------------------------------
__global__ __launch_bounds__(256, 1) void proj_kernel(
    const float* __restrict__ bp, float* __restrict__ y)
{
    extern __shared__ char dsm[];
    const uint32_t sb = smem_u32(dsm);
    const int t = threadIdx.x, lane = t & 31, w = t >> 5, wr = w >> 2, wc = w & 3;
    const int m0 = blockIdx.y * 128, n0 = blockIdx.x * 128;

    const int row = t >> 1, hf = t & 1;
    const int mrow = m0 + row, b_ = mrow >> 11, t_ = mrow & (Tt - 1);
    const __nv_bfloat16* bh = g_w_hi + (size_t)3*589824 + (size_t)(n0+row)*768 + hf*32;
    const __nv_bfloat16* bl = g_w_lo + (size_t)3*589824 + (size_t)(n0+row)*768 + hf*32;
    const uint32_t doff = (uint32_t)(row*144 + hf*64);

    float acc[4][4][4] = {};
    issue4(sb + doff,
           g_y_hi + (((size_t)(b_*Hh + 0))*Tt + t_)*Dd + hf*32,
           g_y_lo + (((size_t)(b_*Hh + 0))*Tt + t_)*Dd + hf*32,
           bh, bl);
    for (int c = 0; c < 12; c++) {
        if (c + 1 < 12)
            issue4(sb + ((c+1)&1)*GBUF + doff,
                   g_y_hi + (((size_t)(b_*Hh + c+1))*Tt + t_)*Dd + hf*32,
                   g_y_lo + (((size_t)(b_*Hh + c+1))*Tt + t_)*Dd + hf*32,
                   bh + (c+1)*64, bl + (c+1)*64);
        if (c + 1 < 12) cp_wait1(); else cp_wait0();
        __syncthreads();
        uint32_t bb = sb + (c & 1)*GBUF;
        consume_128x128(bb, bb+18432, bb+36864, bb+55296, wr, wc, lane, acc);
        __syncthreads();
    }
    const int r0 = lane >> 2, cp2 = (lane & 3)*2;
    #pragma unroll
    for (int i = 0; i < 4; i++) {
        int m = m0 + wr*64 + i*16 + r0;
        #pragma unroll
        for (int j = 0; j < 4; j++) {
            int n = n0 + wc*32 + j*8 + cp2;
            float2 bv = *(const float2*)&bp[n];
            *(float2*)&y[(size_t)m*Cc + n] =
                make_float2(acc[i][j][0] + bv.x, acc[i][j][1] + bv.y);
            *(float2*)&y[(size_t)(m+8)*Cc + n] =
                make_float2(acc[i][j][2] + bv.x, acc[i][j][3] + bv.y);
        }
    }
}

// ---------------------------------------------------------------------------
extern "C" void kernel_launch(void* const* d_in, const int* in_sizes, int n_in,
                              void* d_out, int out_size)
{
    (void)in_sizes; (void)n_in; (void)out_size;
    const float* x  = (const float*)d_in[0];
    const float* Wq = (const float*)d_in[1];
    const float* Wk = (const float*)d_in[2];
    const float* Wv = (const float*)d_in[3];
    const float* Wp = (const float*)d_in[4];
    const float* bp = (const float*)d_in[5];
    const float* rb = (const float*)d_in[6];
    float* y   = (float*)d_out;
    float* att = y + (size_t)Bb * Tt * Cc;

    static int inited = 0;
    if (!inited) {
        cudaFuncSetAttribute(qkv_kernel,    cudaFuncAttributeMaxDynamicSharedMemorySize, 2*GBUF);
        cudaFuncSetAttribute(logits_kernel, cudaFuncAttributeMaxDynamicSharedMemorySize, GBUF);
        cudaFuncSetAttribute(av_kernel,     cudaFuncAttributeMaxDynamicSharedMemorySize, AV2_SMEM);
        cudaFuncSetAttribute(proj_kernel,   cudaFuncAttributeMaxDynamicSharedMemorySize, 2*GBUF);
        inited = 1;
    }

    prep_kernel   <<<dim3(3072, 5), 256>>>(x, Wq, Wk, Wv, Wp);
    qkv_kernel    <<<dim3(6, 32, 3), 256, 2*GBUF>>>();
    rope_prep     <<<128, 256>>>();
    rope_kernel   <<<NBH*Tt*8/256, 256>>>();
    vT_kernel     <<<dim3(64, 2, NBH), 256>>>();
    logits_kernel <<<dim3(16, 16, NBH), 256, GBUF>>>(rb, att);
    softmax_kernel<<<NBH*Tt, 256>>>(att);
    av_kernel     <<<dim3(16, NBH), 256, AV2_SMEM>>>(att);
    proj_kernel   <<<dim3(6, 32), 256, 2*GBUF>>>(bp, y);
}